// round 2
// baseline (speedup 1.0000x reference)
#include <cuda_runtime.h>

// Problem constants
#define BB 256      // batch
#define TT 2000     // seq len
#define HH 64       // hidden
#define G4 256      // 4*H
#define BT (BB*TT)  // 512000

// Scratch (allocation-free rule: __device__ globals)
__device__ float g_xp[(size_t)BT * G4];   // [t][b][gate j] fp32, 524 MB
__device__ float g_hf[BB * HH];
__device__ float g_hb[BB * HH];

typedef unsigned long long u64;

__device__ __forceinline__ u64 fma2(u64 a, u64 b, u64 c) {
    u64 d;
    asm("fma.rn.f32x2 %0, %1, %2, %3;" : "=l"(d) : "l"(a), "l"(b), "l"(c));
    return d;
}
__device__ __forceinline__ u64 pack2(float lo, float hi) {
    u64 d;
    asm("mov.b64 %0, {%1, %2};" : "=l"(d) : "f"(lo), "f"(hi));
    return d;
}
__device__ __forceinline__ float hsum2(u64 a) {
    float lo, hi;
    asm("mov.b64 {%0, %1}, %2;" : "=f"(lo), "=f"(hi) : "l"(a));
    return lo + hi;
}
__device__ __forceinline__ float sigmoid_(float x) {
    return 1.0f / (1.0f + __expf(-x));
}
__device__ __forceinline__ float tanh_(float x) {
    // tanh(x) = 2*sigmoid(2x) - 1; saturates correctly at +-inf
    return 2.0f / (1.0f + __expf(-2.0f * x)) - 1.0f;
}

// ---------------------------------------------------------------------------
// K1: xp_f[t][b][j] = sum_k emb[x[b][t]][k] * w_ih_f[j][k] + b_ih_f[j] + b_hh_f[j]
// thread j (0..255) owns w row j in registers (32 f32x2). 8 rows (b,t) per tile.
// ---------------------------------------------------------------------------
__global__ void __launch_bounds__(256) k_xp(
    const int* __restrict__ x, const float* __restrict__ emb,
    const float* __restrict__ w, const float* __restrict__ b1,
    const float* __restrict__ b2)
{
    __shared__ __align__(16) float sh_e[8 * 64];
    const int j = threadIdx.x;

    u64 w2[32];
#pragma unroll
    for (int k2 = 0; k2 < 32; ++k2) {
        float2 wv = *(const float2*)&w[j * 64 + 2 * k2];
        w2[k2] = pack2(wv.x, wv.y);
    }
    const float bias = b1[j] + b2[j];

    const int ntiles = BT / 8;  // 64000
    for (int tile = blockIdx.x; tile < ntiles; tile += gridDim.x) {
        const int m0 = tile * 8;
        // load 8 embedding rows (gathered, padding_idx=0 -> zero row)
#pragma unroll
        for (int i = j; i < 512; i += 256) {
            int r = i >> 6, k = i & 63;
            int m = m0 + r;
            int b = m & (BB - 1);
            int t = m >> 8;
            int idx = x[b * TT + t];
            sh_e[i] = (idx == 0) ? 0.0f : emb[idx * HH + k];
        }
        __syncthreads();
        const ulonglong2* ep = (const ulonglong2*)sh_e;
#pragma unroll
        for (int r = 0; r < 8; ++r) {
            u64 acc = 0ull;  // (0.0f, 0.0f)
#pragma unroll
            for (int k4 = 0; k4 < 16; ++k4) {
                ulonglong2 ev = ep[r * 16 + k4];
                acc = fma2(w2[2 * k4], ev.x, acc);
                acc = fma2(w2[2 * k4 + 1], ev.y, acc);
            }
            g_xp[(size_t)(m0 + r) * G4 + j] = hsum2(acc) + bias;
        }
        __syncthreads();
    }
}

// ---------------------------------------------------------------------------
// K2: forward LSTM scan. 128 CTAs x 2 batch rows, no cross-CTA sync.
// thread j computes gate pre-activation column j for both rows per step.
// ---------------------------------------------------------------------------
__global__ void __launch_bounds__(256) k_scan(const float* __restrict__ whh)
{
    __shared__ __align__(16) float h_sh[2 * 64];
    __shared__ float g_sh[2 * 256];
    const int j = threadIdx.x;
    const int b0 = blockIdx.x * 2;

    u64 w2[32];
#pragma unroll
    for (int k2 = 0; k2 < 32; ++k2) {
        float2 wv = *(const float2*)&whh[j * 64 + 2 * k2];
        w2[k2] = pack2(wv.x, wv.y);
    }

    if (j < 128) h_sh[j] = 0.0f;
    float c = 0.0f;
    __syncthreads();

    const float* __restrict__ xp = g_xp;
    const size_t base0 = (size_t)b0 * G4 + j;  // full offset: t*65536 + b*256 + j
    float xc0 = xp[base0];
    float xc1 = xp[base0 + 256];
    float xn0 = xp[base0 + 65536];
    float xn1 = xp[base0 + 65536 + 256];

    const int gate = j >> 6;  // 0:i 1:f 2:g 3:o

#pragma unroll 2
    for (int t = 0; t < TT; ++t) {
        // distance-2 prefetch
        float xf0 = 0.0f, xf1 = 0.0f;
        if (t + 2 < TT) {
            size_t o = base0 + (size_t)(t + 2) * 65536;
            xf0 = xp[o];
            xf1 = xp[o + 256];
        }

        // recurrent GEMM: g[b][j] = h[b] . whh[j]
        const ulonglong2* hp = (const ulonglong2*)h_sh;
        u64 a0 = 0ull, a1 = 0ull;
#pragma unroll
        for (int k4 = 0; k4 < 16; ++k4) {
            ulonglong2 h0 = hp[k4];
            ulonglong2 h1 = hp[16 + k4];
            a0 = fma2(w2[2 * k4], h0.x, a0);
            a0 = fma2(w2[2 * k4 + 1], h0.y, a0);
            a1 = fma2(w2[2 * k4], h1.x, a1);
            a1 = fma2(w2[2 * k4 + 1], h1.y, a1);
        }
        float p0 = hsum2(a0) + xc0;
        float p1 = hsum2(a1) + xc1;

        float v0, v1;
        if (gate == 2) { v0 = tanh_(p0); v1 = tanh_(p1); }
        else           { v0 = sigmoid_(p0); v1 = sigmoid_(p1); }
        g_sh[j] = v0;
        g_sh[256 + j] = v1;
        __syncthreads();

        if (j < 128) {
            int u = j & 63, bb = j >> 6;
            const float* gs = g_sh + bb * 256;
            float iv = gs[u];
            float fv = gs[64 + u];
            float gv = gs[128 + u];
            float ov = gs[192 + u];
            c = fv * c + iv * gv;
            h_sh[bb * 64 + u] = ov * tanh_(c);
        }
        __syncthreads();

        xc0 = xn0; xc1 = xn1; xn0 = xf0; xn1 = xf1;
    }

    if (j < 128) {
        int u = j & 63, bb = j >> 6;
        g_hf[(b0 + bb) * HH + u] = h_sh[bb * 64 + u];
    }
}

// ---------------------------------------------------------------------------
// K3: backward LSTM needs only ONE step (hs_b[0]) from zero state at t=T-1:
//     g = emb[x[b][T-1]] @ w_ih_b^T + b_ih_b + b_hh_b; c = i*g; h = o*tanh(c)
// ---------------------------------------------------------------------------
__global__ void __launch_bounds__(256) k_bwd(
    const int* __restrict__ x, const float* __restrict__ emb,
    const float* __restrict__ w, const float* __restrict__ b1,
    const float* __restrict__ b2)
{
    __shared__ __align__(16) float e_sh[64];
    __shared__ float g_sh[256];
    const int j = threadIdx.x;
    const int b = blockIdx.x;

    if (j < 64) {
        int idx = x[b * TT + (TT - 1)];
        e_sh[j] = (idx == 0) ? 0.0f : emb[idx * HH + j];
    }
    __syncthreads();

    float acc = b1[j] + b2[j];
    const ulonglong2* ep = (const ulonglong2*)e_sh;
    u64 a2 = 0ull;
#pragma unroll
    for (int k4 = 0; k4 < 16; ++k4) {
        float2 wv0 = *(const float2*)&w[j * 64 + 4 * k4];
        float2 wv1 = *(const float2*)&w[j * 64 + 4 * k4 + 2];
        ulonglong2 ev = ep[k4];
        a2 = fma2(pack2(wv0.x, wv0.y), ev.x, a2);
        a2 = fma2(pack2(wv1.x, wv1.y), ev.y, a2);
    }
    acc += hsum2(a2);

    const int gate = j >> 6;
    g_sh[j] = (gate == 2) ? tanh_(acc) : sigmoid_(acc);
    __syncthreads();

    if (j < 64) {
        float iv = g_sh[j];
        float gv = g_sh[128 + j];
        float ov = g_sh[192 + j];
        float cc = iv * gv;               // f*c0 = 0
        g_hb[b * HH + j] = ov * tanh_(cc);
    }
}

// ---------------------------------------------------------------------------
// K4: out[b][c] = concat(hf[b], hb[b]) . w_fc[c] + b_fc[c]   (256 x 12)
// ---------------------------------------------------------------------------
__global__ void k_fc(const float* __restrict__ wfc, const float* __restrict__ bfc,
                     float* __restrict__ out)
{
    int t = blockIdx.x * blockDim.x + threadIdx.x;
    if (t >= BB * 12) return;
    int b = t / 12, cc = t % 12;
    float s = bfc[cc];
#pragma unroll
    for (int k = 0; k < 64; ++k)
        s += g_hf[b * 64 + k] * wfc[cc * 128 + k];
#pragma unroll
    for (int k = 0; k < 64; ++k)
        s += g_hb[b * 64 + k] * wfc[cc * 128 + 64 + k];
    out[t] = s;
}

// ---------------------------------------------------------------------------
extern "C" void kernel_launch(void* const* d_in, const int* in_sizes, int n_in,
                              void* d_out, int out_size)
{
    const int*   x      = (const int*)d_in[0];
    const float* emb    = (const float*)d_in[1];
    const float* w_ih_f = (const float*)d_in[2];
    const float* w_hh_f = (const float*)d_in[3];
    const float* b_ih_f = (const float*)d_in[4];
    const float* b_hh_f = (const float*)d_in[5];
    const float* w_ih_b = (const float*)d_in[6];
    const float* w_hh_b = (const float*)d_in[7];
    const float* b_ih_b = (const float*)d_in[8];
    const float* b_hh_b = (const float*)d_in[9];
    const float* w_fc   = (const float*)d_in[10];
    const float* b_fc   = (const float*)d_in[11];
    float* out = (float*)d_out;

    k_xp<<<1024, 256>>>(x, emb, w_ih_f, b_ih_f, b_hh_f);
    k_scan<<<128, 256>>>(w_hh_f);
    k_bwd<<<256, 256>>>(x, emb, w_ih_b, b_ih_b, b_hh_b);
    k_fc<<<(BB * 12 + 127) / 128, 128>>>(w_fc, b_fc, out);
}

// round 3
// speedup vs baseline: 1.5356x; 1.5356x over previous
#include <cuda_runtime.h>

// Problem constants
#define BB 256      // batch
#define TT 2000     // seq len
#define HH 64       // hidden
#define G4 256      // 4*H
#define VV 2000     // vocab

// Scratch (allocation-free rule: __device__ globals)
__device__ float g_proj[(size_t)VV * G4];   // [v][j] fp32, 2 MB (L2-resident)
__device__ float g_hf[BB * HH];
__device__ float g_hb[BB * HH];

typedef unsigned long long u64;

__device__ __forceinline__ u64 fma2(u64 a, u64 b, u64 c) {
    u64 d;
    asm("fma.rn.f32x2 %0, %1, %2, %3;" : "=l"(d) : "l"(a), "l"(b), "l"(c));
    return d;
}
__device__ __forceinline__ u64 pack2(float lo, float hi) {
    u64 d;
    asm("mov.b64 %0, {%1, %2};" : "=l"(d) : "f"(lo), "f"(hi));
    return d;
}
__device__ __forceinline__ float hsum2(u64 a) {
    float lo, hi;
    asm("mov.b64 {%0, %1}, %2;" : "=f"(lo), "=f"(hi) : "l"(a));
    return lo + hi;
}
__device__ __forceinline__ float sigmoid_(float x) {
    return 1.0f / (1.0f + __expf(-x));
}
__device__ __forceinline__ float tanh_(float x) {
    return 2.0f / (1.0f + __expf(-2.0f * x)) - 1.0f;
}

// ---------------------------------------------------------------------------
// K0: proj[v][j] = sum_k emb[v][k] * w_ih_f[j][k] + b_ih_f[j] + b_hh_f[j]
// (v == 0 is the padding row: embedding treated as zero -> proj = bias)
// thread j owns w row j in registers; 8 vocab rows per tile.
// ---------------------------------------------------------------------------
__global__ void __launch_bounds__(256) k_proj(
    const float* __restrict__ emb, const float* __restrict__ w,
    const float* __restrict__ b1, const float* __restrict__ b2)
{
    __shared__ __align__(16) float sh_e[8 * 64];
    const int j = threadIdx.x;

    u64 w2[32];
#pragma unroll
    for (int k2 = 0; k2 < 32; ++k2) {
        float2 wv = *(const float2*)&w[j * 64 + 2 * k2];
        w2[k2] = pack2(wv.x, wv.y);
    }
    const float bias = b1[j] + b2[j];

    const int v0 = blockIdx.x * 8;
    // load 8 embedding rows (row 0 -> zeros, padding_idx)
#pragma unroll
    for (int i = j; i < 512; i += 256) {
        int r = i >> 6, k = i & 63;
        int v = v0 + r;
        sh_e[i] = (v == 0 || v >= VV) ? 0.0f : emb[v * HH + k];
    }
    __syncthreads();
    const ulonglong2* ep = (const ulonglong2*)sh_e;
#pragma unroll
    for (int r = 0; r < 8; ++r) {
        int v = v0 + r;
        if (v >= VV) break;
        u64 acc = 0ull;
#pragma unroll
        for (int k4 = 0; k4 < 16; ++k4) {
            ulonglong2 ev = ep[r * 16 + k4];
            acc = fma2(w2[2 * k4], ev.x, acc);
            acc = fma2(w2[2 * k4 + 1], ev.y, acc);
        }
        g_proj[(size_t)v * G4 + j] = hsum2(acc) + bias;
    }
}

// ---------------------------------------------------------------------------
// K2: forward LSTM scan. 128 CTAs x 2 batch rows, no cross-CTA sync.
// Input projections gathered on the fly from the L2-resident proj table.
// ---------------------------------------------------------------------------
__global__ void __launch_bounds__(256) k_scan(
    const int* __restrict__ x, const float* __restrict__ whh)
{
    __shared__ __align__(16) float h_sh[2 * 64];
    __shared__ float g_sh[2 * 256];
    const int j = threadIdx.x;
    const int b0 = blockIdx.x * 2;

    u64 w2[32];
#pragma unroll
    for (int k2 = 0; k2 < 32; ++k2) {
        float2 wv = *(const float2*)&whh[j * 64 + 2 * k2];
        w2[k2] = pack2(wv.x, wv.y);
    }

    if (j < 128) h_sh[j] = 0.0f;
    float c = 0.0f;
    __syncthreads();

    const float* __restrict__ proj = g_proj;
    const int* __restrict__ xr0 = x + (size_t)b0 * TT;
    const int* __restrict__ xr1 = x + (size_t)(b0 + 1) * TT;

    // distance-2 projection prefetch (L2 hits, ~250 cyc, covered by 2 steps)
    float xc0 = proj[(size_t)xr0[0] * G4 + j];
    float xc1 = proj[(size_t)xr1[0] * G4 + j];
    float xn0 = proj[(size_t)xr0[1] * G4 + j];
    float xn1 = proj[(size_t)xr1[1] * G4 + j];

    const int gate = j >> 6;  // 0:i 1:f 2:g 3:o

#pragma unroll 2
    for (int t = 0; t < TT; ++t) {
        float xf0 = 0.0f, xf1 = 0.0f;
        if (t + 2 < TT) {
            xf0 = proj[(size_t)xr0[t + 2] * G4 + j];
            xf1 = proj[(size_t)xr1[t + 2] * G4 + j];
        }

        // recurrent GEMM: g[b][j] = h[b] . whh[j]  (4 accumulators, 16-deep chains)
        const ulonglong2* hp = (const ulonglong2*)h_sh;
        u64 a0 = 0ull, a1 = 0ull, a2 = 0ull, a3 = 0ull;
#pragma unroll
        for (int k4 = 0; k4 < 16; ++k4) {
            ulonglong2 h0 = hp[k4];
            ulonglong2 h1 = hp[16 + k4];
            a0 = fma2(w2[2 * k4], h0.x, a0);
            a1 = fma2(w2[2 * k4 + 1], h0.y, a1);
            a2 = fma2(w2[2 * k4], h1.x, a2);
            a3 = fma2(w2[2 * k4 + 1], h1.y, a3);
        }
        float p0 = hsum2(a0) + hsum2(a1) + xc0;
        float p1 = hsum2(a2) + hsum2(a3) + xc1;

        float v0, v1;
        if (gate == 2) { v0 = tanh_(p0); v1 = tanh_(p1); }
        else           { v0 = sigmoid_(p0); v1 = sigmoid_(p1); }
        g_sh[j] = v0;
        g_sh[256 + j] = v1;
        __syncthreads();

        if (j < 128) {
            int u = j & 63, bb = j >> 6;
            const float* gs = g_sh + bb * 256;
            float iv = gs[u];
            float fv = gs[64 + u];
            float gv = gs[128 + u];
            float ov = gs[192 + u];
            c = fv * c + iv * gv;
            h_sh[bb * 64 + u] = ov * tanh_(c);
        }
        __syncthreads();

        xc0 = xn0; xc1 = xn1; xn0 = xf0; xn1 = xf1;
    }

    if (j < 128) {
        int u = j & 63, bb = j >> 6;
        g_hf[(b0 + bb) * HH + u] = h_sh[bb * 64 + u];
    }
}

// ---------------------------------------------------------------------------
// K3: backward LSTM needs only ONE step (hs_b[0]) from zero state at t=T-1:
//     g = emb[x[b][T-1]] @ w_ih_b^T + b_ih_b + b_hh_b; c = i*g; h = o*tanh(c)
// ---------------------------------------------------------------------------
__global__ void __launch_bounds__(256) k_bwd(
    const int* __restrict__ x, const float* __restrict__ emb,
    const float* __restrict__ w, const float* __restrict__ b1,
    const float* __restrict__ b2)
{
    __shared__ __align__(16) float e_sh[64];
    __shared__ float g_sh[256];
    const int j = threadIdx.x;
    const int b = blockIdx.x;

    if (j < 64) {
        int idx = x[b * TT + (TT - 1)];
        e_sh[j] = (idx == 0) ? 0.0f : emb[idx * HH + j];
    }
    __syncthreads();

    float acc = b1[j] + b2[j];
    const ulonglong2* ep = (const ulonglong2*)e_sh;
    u64 a2 = 0ull;
#pragma unroll
    for (int k4 = 0; k4 < 16; ++k4) {
        float2 wv0 = *(const float2*)&w[j * 64 + 4 * k4];
        float2 wv1 = *(const float2*)&w[j * 64 + 4 * k4 + 2];
        ulonglong2 ev = ep[k4];
        a2 = fma2(pack2(wv0.x, wv0.y), ev.x, a2);
        a2 = fma2(pack2(wv1.x, wv1.y), ev.y, a2);
    }
    acc += hsum2(a2);

    const int gate = j >> 6;
    g_sh[j] = (gate == 2) ? tanh_(acc) : sigmoid_(acc);
    __syncthreads();

    if (j < 64) {
        float iv = g_sh[j];
        float gv = g_sh[128 + j];
        float ov = g_sh[192 + j];
        float cc = iv * gv;               // f*c0 = 0
        g_hb[b * HH + j] = ov * tanh_(cc);
    }
}

// ---------------------------------------------------------------------------
// K4: out[b][c] = concat(hf[b], hb[b]) . w_fc[c] + b_fc[c]   (256 x 12)
// ---------------------------------------------------------------------------
__global__ void k_fc(const float* __restrict__ wfc, const float* __restrict__ bfc,
                     float* __restrict__ out)
{
    int t = blockIdx.x * blockDim.x + threadIdx.x;
    if (t >= BB * 12) return;
    int b = t / 12, cc = t % 12;
    float s = bfc[cc];
#pragma unroll
    for (int k = 0; k < 64; ++k)
        s += g_hf[b * 64 + k] * wfc[cc * 128 + k];
#pragma unroll
    for (int k = 0; k < 64; ++k)
        s += g_hb[b * 64 + k] * wfc[cc * 128 + 64 + k];
    out[t] = s;
}

// ---------------------------------------------------------------------------
extern "C" void kernel_launch(void* const* d_in, const int* in_sizes, int n_in,
                              void* d_out, int out_size)
{
    const int*   x      = (const int*)d_in[0];
    const float* emb    = (const float*)d_in[1];
    const float* w_ih_f = (const float*)d_in[2];
    const float* w_hh_f = (const float*)d_in[3];
    const float* b_ih_f = (const float*)d_in[4];
    const float* b_hh_f = (const float*)d_in[5];
    const float* w_ih_b = (const float*)d_in[6];
    const float* w_hh_b = (const float*)d_in[7];
    const float* b_ih_b = (const float*)d_in[8];
    const float* b_hh_b = (const float*)d_in[9];
    const float* w_fc   = (const float*)d_in[10];
    const float* b_fc   = (const float*)d_in[11];
    float* out = (float*)d_out;

    k_proj<<<(VV + 7) / 8, 256>>>(emb, w_ih_f, b_ih_f, b_hh_f);
    k_scan<<<128, 256>>>(x, w_hh_f);
    k_bwd<<<256, 256>>>(x, emb, w_ih_b, b_ih_b, b_hh_b);
    k_fc<<<(BB * 12 + 127) / 128, 128>>>(w_fc, b_fc, out);
}

// round 4
// speedup vs baseline: 1.6857x; 1.0977x over previous
#include <cuda_runtime.h>

// Problem constants
#define BB 256      // batch
#define TT 2000     // seq len
#define HH 64       // hidden
#define G4 256      // 4*H
#define VV 2000     // vocab

// Scratch (allocation-free rule: __device__ globals)
__device__ float g_proj[(size_t)VV * G4];   // [v][j] fp32, 2 MB (L2-resident)
__device__ float g_hf[BB * HH];

typedef unsigned long long u64;

__device__ __forceinline__ u64 fma2(u64 a, u64 b, u64 c) {
    u64 d;
    asm("fma.rn.f32x2 %0, %1, %2, %3;" : "=l"(d) : "l"(a), "l"(b), "l"(c));
    return d;
}
__device__ __forceinline__ u64 pack2(float lo, float hi) {
    u64 d;
    asm("mov.b64 %0, {%1, %2};" : "=l"(d) : "f"(lo), "f"(hi));
    return d;
}
__device__ __forceinline__ float hsum2(u64 a) {
    float lo, hi;
    asm("mov.b64 {%0, %1}, %2;" : "=f"(lo), "=f"(hi) : "l"(a));
    return lo + hi;
}
__device__ __forceinline__ float sigmoid_(float x) {
    return 1.0f / (1.0f + __expf(-x));
}
__device__ __forceinline__ float tanh_(float x) {
    return 2.0f / (1.0f + __expf(-2.0f * x)) - 1.0f;
}
__device__ __forceinline__ void barhalf(int half) {
    asm volatile("bar.sync %0, 128;" :: "r"(half + 1) : "memory");
}

// ---------------------------------------------------------------------------
// K0: proj[v][j] = sum_k emb[v][k] * w_ih_f[j][k] + b_ih_f[j] + b_hh_f[j]
// ---------------------------------------------------------------------------
__global__ void __launch_bounds__(256) k_proj(
    const float* __restrict__ emb, const float* __restrict__ w,
    const float* __restrict__ b1, const float* __restrict__ b2)
{
    __shared__ __align__(16) float sh_e[8 * 64];
    const int j = threadIdx.x;

    u64 w2[32];
#pragma unroll
    for (int k2 = 0; k2 < 32; ++k2) {
        float2 wv = *(const float2*)&w[j * 64 + 2 * k2];
        w2[k2] = pack2(wv.x, wv.y);
    }
    const float bias = b1[j] + b2[j];

    const int v0 = blockIdx.x * 8;
#pragma unroll
    for (int i = j; i < 512; i += 256) {
        int r = i >> 6, k = i & 63;
        int v = v0 + r;
        sh_e[i] = (v == 0 || v >= VV) ? 0.0f : emb[v * HH + k];
    }
    __syncthreads();
    const ulonglong2* ep = (const ulonglong2*)sh_e;
#pragma unroll
    for (int r = 0; r < 8; ++r) {
        int v = v0 + r;
        if (v >= VV) break;
        u64 acc = 0ull;
#pragma unroll
        for (int k4 = 0; k4 < 16; ++k4) {
            ulonglong2 ev = ep[r * 16 + k4];
            acc = fma2(w2[2 * k4], ev.x, acc);
            acc = fma2(w2[2 * k4 + 1], ev.y, acc);
        }
        g_proj[(size_t)v * G4 + j] = hsum2(acc) + bias;
    }
}

// ---------------------------------------------------------------------------
// K2: forward LSTM scan.
// 128 CTAs x 2 batch rows. Warps 0-3 = row 0, warps 4-7 = row 1 (independent
// named barriers). Quad-gate lane layout: lane l -> (gate=l&3, unit=wq*8+l>>2),
// each thread covers units u0 and u0+32 for its gate. Gate exchange via shfl,
// one barrier per step with ping-pong h buffers.
// ---------------------------------------------------------------------------
__global__ void __launch_bounds__(256, 1) k_scan(
    const int* __restrict__ x, const float* __restrict__ whh)
{
    __shared__ __align__(16) float h_sh[2][2][64];  // [buf][half][unit]
    const int tid = threadIdx.x;
    const int w = tid >> 5, l = tid & 31;
    const int half = w >> 2;          // batch row within CTA
    const int wq = w & 3;             // warp within half
    const int gate = l & 3;           // 0:i 1:f 2:g 3:o
    const int u0 = wq * 8 + (l >> 2); // 0..31
    const int u1 = u0 + 32;
    const int b = blockIdx.x * 2 + half;
    const int j0 = gate * 64 + u0;
    const int j1 = gate * 64 + u1;

    // weight rows j0, j1 in registers (k-packed f32x2)
    u64 wa[32], wb[32];
#pragma unroll
    for (int k2 = 0; k2 < 32; ++k2) {
        float2 va = *(const float2*)&whh[j0 * 64 + 2 * k2];
        float2 vb = *(const float2*)&whh[j1 * 64 + 2 * k2];
        wa[k2] = pack2(va.x, va.y);
        wb[k2] = pack2(vb.x, vb.y);
    }

    // zero step-0 read buffer
    if (l < 16) h_sh[0][half][wq * 16 + l] = 0.0f;
    float c0 = 0.0f, c1 = 0.0f;

    // activation constants: gate==2 -> tanh(p) = 2*sigmoid(2p)-1
    const float sc = (gate == 2) ? 2.0f : 1.0f;
    const float mv = (gate == 2) ? 2.0f : 1.0f;
    const float av = (gate == 2) ? -1.0f : 0.0f;

    const float* __restrict__ proj = g_proj;
    const int* __restrict__ xr = x + (size_t)b * TT;

    // distance-2 prefetch of input projections (L2-resident table)
    int i0 = xr[0], i1 = xr[1];
    float xc0 = proj[i0 * G4 + j0], xc1 = proj[i0 * G4 + j1];
    float xn0 = proj[i1 * G4 + j0], xn1 = proj[i1 * G4 + j1];

    barhalf(half);  // h init visible

    for (int t = 0; t < TT; ++t) {
        float xf0 = 0.0f, xf1 = 0.0f;
        if (t + 2 < TT) {
            int i2 = xr[t + 2];
            xf0 = proj[i2 * G4 + j0];
            xf1 = proj[i2 * G4 + j1];
        }

        // recurrent dots: p = h . whh[j] + xc
        const ulonglong2* hp = (const ulonglong2*)h_sh[t & 1][half];
        u64 a0 = 0ull, a1 = 0ull, b0 = 0ull, b1 = 0ull;
#pragma unroll
        for (int k4 = 0; k4 < 16; ++k4) {
            ulonglong2 hv = hp[k4];
            a0 = fma2(wa[2 * k4],     hv.x, a0);
            a1 = fma2(wa[2 * k4 + 1], hv.y, a1);
            b0 = fma2(wb[2 * k4],     hv.x, b0);
            b1 = fma2(wb[2 * k4 + 1], hv.y, b1);
        }
        float p0 = hsum2(a0) + hsum2(a1) + xc0;
        float p1 = hsum2(b0) + hsum2(b1) + xc1;

        // branchless activation
        float r0 = 1.0f / (1.0f + __expf(-sc * p0));
        float r1 = 1.0f / (1.0f + __expf(-sc * p1));
        float v0 = fmaf(mv, r0, av);
        float v1 = fmaf(mv, r1, av);

        // quad exchange: lane gate==0 gathers f,g,o from lanes +1,+2,+3
        float f0 = __shfl_down_sync(0xffffffffu, v0, 1);
        float g0 = __shfl_down_sync(0xffffffffu, v0, 2);
        float o0 = __shfl_down_sync(0xffffffffu, v0, 3);
        float f1 = __shfl_down_sync(0xffffffffu, v1, 1);
        float g1 = __shfl_down_sync(0xffffffffu, v1, 2);
        float o1 = __shfl_down_sync(0xffffffffu, v1, 3);

        if (gate == 0) {
            c0 = f0 * c0 + v0 * g0;
            c1 = f1 * c1 + v1 * g1;
            float h0 = o0 * tanh_(c0);
            float h1 = o1 * tanh_(c1);
            if (t == TT - 1) {
                g_hf[b * HH + u0] = h0;
                g_hf[b * HH + u1] = h1;
            } else {
                h_sh[(t + 1) & 1][half][u0] = h0;
                h_sh[(t + 1) & 1][half][u1] = h1;
            }
        }
        barhalf(half);

        xc0 = xn0; xc1 = xn1; xn0 = xf0; xn1 = xf1;
    }
}

// ---------------------------------------------------------------------------
// K3: fused tail. One block per batch row:
//   1) backward LSTM single step (hs_b[0]) from zero state at t=T-1
//   2) fc: out[b][c] = concat(hf[b], hb[b]) . w_fc[c] + b_fc[c]
// ---------------------------------------------------------------------------
__global__ void __launch_bounds__(256) k_tail(
    const int* __restrict__ x, const float* __restrict__ emb,
    const float* __restrict__ w, const float* __restrict__ b1,
    const float* __restrict__ b2, const float* __restrict__ wfc,
    const float* __restrict__ bfc, float* __restrict__ out)
{
    __shared__ __align__(16) float e_sh[64];
    __shared__ float g_sh[256];
    __shared__ float hb_sh[64];
    const int j = threadIdx.x;
    const int b = blockIdx.x;

    if (j < 64) {
        int idx = x[b * TT + (TT - 1)];
        e_sh[j] = (idx == 0) ? 0.0f : emb[idx * HH + j];
    }
    __syncthreads();

    float acc = b1[j] + b2[j];
    const ulonglong2* ep = (const ulonglong2*)e_sh;
    u64 a2 = 0ull;
#pragma unroll
    for (int k4 = 0; k4 < 16; ++k4) {
        float2 wv0 = *(const float2*)&w[j * 64 + 4 * k4];
        float2 wv1 = *(const float2*)&w[j * 64 + 4 * k4 + 2];
        ulonglong2 ev = ep[k4];
        a2 = fma2(pack2(wv0.x, wv0.y), ev.x, a2);
        a2 = fma2(pack2(wv1.x, wv1.y), ev.y, a2);
    }
    acc += hsum2(a2);

    const int gate = j >> 6;
    g_sh[j] = (gate == 2) ? tanh_(acc) : sigmoid_(acc);
    __syncthreads();

    if (j < 64) {
        float iv = g_sh[j];
        float gv = g_sh[128 + j];
        float ov = g_sh[192 + j];
        float cc = iv * gv;               // f*c0 = 0
        hb_sh[j] = ov * tanh_(cc);
    }
    __syncthreads();

    if (j < 12) {
        float s = bfc[j];
        const float* hf = g_hf + b * HH;
#pragma unroll
        for (int k = 0; k < 64; ++k)
            s += hf[k] * wfc[j * 128 + k];
#pragma unroll
        for (int k = 0; k < 64; ++k)
            s += hb_sh[k] * wfc[j * 128 + 64 + k];
        out[b * 12 + j] = s;
    }
}

// ---------------------------------------------------------------------------
extern "C" void kernel_launch(void* const* d_in, const int* in_sizes, int n_in,
                              void* d_out, int out_size)
{
    const int*   x      = (const int*)d_in[0];
    const float* emb    = (const float*)d_in[1];
    const float* w_ih_f = (const float*)d_in[2];
    const float* w_hh_f = (const float*)d_in[3];
    const float* b_ih_f = (const float*)d_in[4];
    const float* b_hh_f = (const float*)d_in[5];
    const float* w_ih_b = (const float*)d_in[6];
    const float* w_hh_b = (const float*)d_in[7];
    const float* b_ih_b = (const float*)d_in[8];
    const float* b_hh_b = (const float*)d_in[9];
    const float* w_fc   = (const float*)d_in[10];
    const float* b_fc   = (const float*)d_in[11];
    float* out = (float*)d_out;

    k_proj<<<(VV + 7) / 8, 256>>>(emb, w_ih_f, b_ih_f, b_hh_f);
    k_scan<<<128, 256>>>(x, w_hh_f);
    k_tail<<<BB, 256>>>(x, emb, w_ih_b, b_ih_b, b_hh_b, w_fc, b_fc, out);
}

// round 5
// speedup vs baseline: 2.5215x; 1.4959x over previous
#include <cuda_runtime.h>

// Problem constants
#define BB 256      // batch
#define TT 2000     // seq len
#define HH 64       // hidden
#define G4 256      // 4*H
#define VV 2000     // vocab

// Scratch (allocation-free rule: __device__ globals)
__device__ float g_proj[(size_t)VV * G4];   // [v][j] fp32, 2 MB (L2-resident)
__device__ float g_hf[BB * HH];

typedef unsigned long long u64;

__device__ __forceinline__ u64 fma2(u64 a, u64 b, u64 c) {
    u64 d;
    asm("fma.rn.f32x2 %0, %1, %2, %3;" : "=l"(d) : "l"(a), "l"(b), "l"(c));
    return d;
}
__device__ __forceinline__ u64 add2(u64 a, u64 b) {
    u64 d;
    asm("add.rn.f32x2 %0, %1, %2;" : "=l"(d) : "l"(a), "l"(b));
    return d;
}
__device__ __forceinline__ u64 pack2(float lo, float hi) {
    u64 d;
    asm("mov.b64 %0, {%1, %2};" : "=l"(d) : "f"(lo), "f"(hi));
    return d;
}
__device__ __forceinline__ float hsum2(u64 a) {
    float lo, hi;
    asm("mov.b64 {%0, %1}, %2;" : "=f"(lo), "=f"(hi) : "l"(a));
    return lo + hi;
}
// MUFU-only fast transcendentals (no fp32 division slow path)
__device__ __forceinline__ float ex2_(float x) {
    float r; asm("ex2.approx.f32 %0, %1;" : "=f"(r) : "f"(x)); return r;
}
__device__ __forceinline__ float rcp_(float x) {
    float r; asm("rcp.approx.f32 %0, %1;" : "=f"(r) : "f"(x)); return r;
}
__device__ __forceinline__ float sigmoid_(float x) {
    return rcp_(1.0f + ex2_(-1.4426950408889634f * x));
}
__device__ __forceinline__ float tanh_(float x) {
    return fmaf(2.0f, rcp_(1.0f + ex2_(-2.8853900817779268f * x)), -1.0f);
}
__device__ __forceinline__ void barhalf(int half) {
    asm volatile("bar.sync %0, 128;" :: "r"(half + 1) : "memory");
}

// ---------------------------------------------------------------------------
// K0: proj[v][j] = sum_k emb[v][k] * w_ih_f[j][k] + b_ih_f[j] + b_hh_f[j]
// ---------------------------------------------------------------------------
__global__ void __launch_bounds__(256) k_proj(
    const float* __restrict__ emb, const float* __restrict__ w,
    const float* __restrict__ b1, const float* __restrict__ b2)
{
    __shared__ __align__(16) float sh_e[8 * 64];
    const int j = threadIdx.x;

    u64 w2[32];
#pragma unroll
    for (int k2 = 0; k2 < 32; ++k2) {
        float2 wv = *(const float2*)&w[j * 64 + 2 * k2];
        w2[k2] = pack2(wv.x, wv.y);
    }
    const float bias = b1[j] + b2[j];

    const int v0 = blockIdx.x * 8;
#pragma unroll
    for (int i = j; i < 512; i += 256) {
        int r = i >> 6, k = i & 63;
        int v = v0 + r;
        sh_e[i] = (v == 0 || v >= VV) ? 0.0f : emb[v * HH + k];
    }
    __syncthreads();
    const ulonglong2* ep = (const ulonglong2*)sh_e;
#pragma unroll
    for (int r = 0; r < 8; ++r) {
        int v = v0 + r;
        if (v >= VV) break;
        u64 acc = 0ull;
#pragma unroll
        for (int k4 = 0; k4 < 16; ++k4) {
            ulonglong2 ev = ep[r * 16 + k4];
            acc = fma2(w2[2 * k4], ev.x, acc);
            acc = fma2(w2[2 * k4 + 1], ev.y, acc);
        }
        g_proj[(size_t)v * G4 + j] = hsum2(acc) + bias;
    }
}

// ---------------------------------------------------------------------------
// K2: forward LSTM scan.
// 128 CTAs x 2 batch rows. Warps 0-3 = row 0, warps 4-7 = row 1 (independent
// named barriers). Quad-gate lane layout, shfl gate exchange, one barrier per
// step with ping-pong h buffers. Branch-free mainloop (last step peeled),
// MUFU-only activations, x indices staged in shared.
// ---------------------------------------------------------------------------
__global__ void __launch_bounds__(256, 1) k_scan(
    const int* __restrict__ x, const float* __restrict__ whh)
{
    __shared__ __align__(16) float h_sh[2][2][64];  // [buf][half][unit]
    __shared__ int xs[2 * TT];                      // both rows' indices, 16 KB
    const int tid = threadIdx.x;
    const int w = tid >> 5, l = tid & 31;
    const int half = w >> 2;          // batch row within CTA
    const int wq = w & 3;             // warp within half
    const int gate = l & 3;           // 0:i 1:f 2:g 3:o
    const int u0 = wq * 8 + (l >> 2); // 0..31
    const int u1 = u0 + 32;
    const int b = blockIdx.x * 2 + half;
    const int j0 = gate * 64 + u0;
    const int j1 = gate * 64 + u1;

    // stage x indices for both rows (contiguous 4000 ints)
    {
        const int* xr = x + (size_t)(blockIdx.x * 2) * TT;
        for (int i = tid; i < 2 * TT; i += 256) xs[i] = xr[i];
    }

    // weight rows j0, j1 in registers (k-packed f32x2)
    u64 wa[32], wb[32];
#pragma unroll
    for (int k2 = 0; k2 < 32; ++k2) {
        float2 va = *(const float2*)&whh[j0 * 64 + 2 * k2];
        float2 vb = *(const float2*)&whh[j1 * 64 + 2 * k2];
        wa[k2] = pack2(va.x, va.y);
        wb[k2] = pack2(vb.x, vb.y);
    }

    // zero step-0 read buffer
    if (l < 16) h_sh[0][half][wq * 16 + l] = 0.0f;
    float c0 = 0.0f, c1 = 0.0f;

    // activation constants (branchless): gate==2 -> tanh(p)=2*sig(2p)-1
    const float sc = (gate == 2) ? -2.8853900817779268f : -1.4426950408889634f;
    const float mv = (gate == 2) ? 2.0f : 1.0f;
    const float av = (gate == 2) ? -1.0f : 0.0f;

    const float* __restrict__ proj = g_proj;
    const int* xsh = xs + half * TT;

    __syncthreads();  // x stage + h init visible

    // distance-2 prefetch of input projections (L2-resident table)
    int i0 = xsh[0], i1 = xsh[1];
    float xc0 = proj[i0 * G4 + j0], xc1 = proj[i0 * G4 + j1];
    float xn0 = proj[i1 * G4 + j0], xn1 = proj[i1 * G4 + j1];

    for (int t = 0; t < TT - 1; ++t) {
        int tp = min(t + 2, TT - 1);      // clamp, branch-free
        int i2 = xsh[tp];
        float xf0 = proj[i2 * G4 + j0];
        float xf1 = proj[i2 * G4 + j1];

        // recurrent dots: p = h . whh[j] + xc  (8-deep f32x2 chains x 4)
        const ulonglong2* hp = (const ulonglong2*)h_sh[t & 1][half];
        u64 a0 = 0ull, a1 = 0ull, a2 = 0ull, a3 = 0ull;
        u64 d0 = 0ull, d1 = 0ull, d2 = 0ull, d3 = 0ull;
#pragma unroll
        for (int k4 = 0; k4 < 8; ++k4) {
            ulonglong2 hv0 = hp[k4];
            ulonglong2 hv1 = hp[8 + k4];
            a0 = fma2(wa[2 * k4],      hv0.x, a0);
            a1 = fma2(wa[2 * k4 + 1],  hv0.y, a1);
            a2 = fma2(wa[16 + 2 * k4], hv1.x, a2);
            a3 = fma2(wa[17 + 2 * k4], hv1.y, a3);
            d0 = fma2(wb[2 * k4],      hv0.x, d0);
            d1 = fma2(wb[2 * k4 + 1],  hv0.y, d1);
            d2 = fma2(wb[16 + 2 * k4], hv1.x, d2);
            d3 = fma2(wb[17 + 2 * k4], hv1.y, d3);
        }
        float p0 = hsum2(add2(add2(a0, a1), add2(a2, a3))) + xc0;
        float p1 = hsum2(add2(add2(d0, d1), add2(d2, d3))) + xc1;

        // branchless MUFU activation
        float v0 = fmaf(mv, rcp_(1.0f + ex2_(sc * p0)), av);
        float v1 = fmaf(mv, rcp_(1.0f + ex2_(sc * p1)), av);

        // quad exchange: lane gate==0 gathers f,g,o from lanes +1,+2,+3
        float f0 = __shfl_down_sync(0xffffffffu, v0, 1);
        float g0 = __shfl_down_sync(0xffffffffu, v0, 2);
        float o0 = __shfl_down_sync(0xffffffffu, v0, 3);
        float f1 = __shfl_down_sync(0xffffffffu, v1, 1);
        float g1 = __shfl_down_sync(0xffffffffu, v1, 2);
        float o1 = __shfl_down_sync(0xffffffffu, v1, 3);

        if (gate == 0) {
            c0 = f0 * c0 + v0 * g0;
            c1 = f1 * c1 + v1 * g1;
            h_sh[(t + 1) & 1][half][u0] = o0 * tanh_(c0);
            h_sh[(t + 1) & 1][half][u1] = o1 * tanh_(c1);
        }
        barhalf(half);

        xc0 = xn0; xc1 = xn1; xn0 = xf0; xn1 = xf1;
    }

    // peeled final step t = TT-1: write h straight to global
    {
        const ulonglong2* hp = (const ulonglong2*)h_sh[(TT - 1) & 1][half];
        u64 a0 = 0ull, a1 = 0ull, a2 = 0ull, a3 = 0ull;
        u64 d0 = 0ull, d1 = 0ull, d2 = 0ull, d3 = 0ull;
#pragma unroll
        for (int k4 = 0; k4 < 8; ++k4) {
            ulonglong2 hv0 = hp[k4];
            ulonglong2 hv1 = hp[8 + k4];
            a0 = fma2(wa[2 * k4],      hv0.x, a0);
            a1 = fma2(wa[2 * k4 + 1],  hv0.y, a1);
            a2 = fma2(wa[16 + 2 * k4], hv1.x, a2);
            a3 = fma2(wa[17 + 2 * k4], hv1.y, a3);
            d0 = fma2(wb[2 * k4],      hv0.x, d0);
            d1 = fma2(wb[2 * k4 + 1],  hv0.y, d1);
            d2 = fma2(wb[16 + 2 * k4], hv1.x, d2);
            d3 = fma2(wb[17 + 2 * k4], hv1.y, d3);
        }
        float p0 = hsum2(add2(add2(a0, a1), add2(a2, a3))) + xc0;
        float p1 = hsum2(add2(add2(d0, d1), add2(d2, d3))) + xc1;
        float v0 = fmaf(mv, rcp_(1.0f + ex2_(sc * p0)), av);
        float v1 = fmaf(mv, rcp_(1.0f + ex2_(sc * p1)), av);
        float f0 = __shfl_down_sync(0xffffffffu, v0, 1);
        float g0 = __shfl_down_sync(0xffffffffu, v0, 2);
        float o0 = __shfl_down_sync(0xffffffffu, v0, 3);
        float f1 = __shfl_down_sync(0xffffffffu, v1, 1);
        float g1 = __shfl_down_sync(0xffffffffu, v1, 2);
        float o1 = __shfl_down_sync(0xffffffffu, v1, 3);
        if (gate == 0) {
            c0 = f0 * c0 + v0 * g0;
            c1 = f1 * c1 + v1 * g1;
            g_hf[b * HH + u0] = o0 * tanh_(c0);
            g_hf[b * HH + u1] = o1 * tanh_(c1);
        }
    }
}

// ---------------------------------------------------------------------------
// K3: fused tail. One block per batch row:
//   1) backward LSTM single step (hs_b[0]) from zero state at t=T-1
//   2) fc: out[b][c] = concat(hf[b], hb[b]) . w_fc[c] + b_fc[c]
// ---------------------------------------------------------------------------
__global__ void __launch_bounds__(256) k_tail(
    const int* __restrict__ x, const float* __restrict__ emb,
    const float* __restrict__ w, const float* __restrict__ b1,
    const float* __restrict__ b2, const float* __restrict__ wfc,
    const float* __restrict__ bfc, float* __restrict__ out)
{
    __shared__ __align__(16) float e_sh[64];
    __shared__ float g_sh[256];
    __shared__ float hb_sh[64];
    const int j = threadIdx.x;
    const int b = blockIdx.x;

    if (j < 64) {
        int idx = x[b * TT + (TT - 1)];
        e_sh[j] = (idx == 0) ? 0.0f : emb[idx * HH + j];
    }
    __syncthreads();

    float acc = b1[j] + b2[j];
    const ulonglong2* ep = (const ulonglong2*)e_sh;
    u64 a2 = 0ull;
#pragma unroll
    for (int k4 = 0; k4 < 16; ++k4) {
        float2 wv0 = *(const float2*)&w[j * 64 + 4 * k4];
        float2 wv1 = *(const float2*)&w[j * 64 + 4 * k4 + 2];
        ulonglong2 ev = ep[k4];
        a2 = fma2(pack2(wv0.x, wv0.y), ev.x, a2);
        a2 = fma2(pack2(wv1.x, wv1.y), ev.y, a2);
    }
    acc += hsum2(a2);

    const int gate = j >> 6;
    g_sh[j] = (gate == 2) ? tanh_(acc) : sigmoid_(acc);
    __syncthreads();

    if (j < 64) {
        float iv = g_sh[j];
        float gv = g_sh[128 + j];
        float ov = g_sh[192 + j];
        float cc = iv * gv;               // f*c0 = 0
        hb_sh[j] = ov * tanh_(cc);
    }
    __syncthreads();

    if (j < 12) {
        float s = bfc[j];
        const float* hf = g_hf + b * HH;
#pragma unroll
        for (int k = 0; k < 64; ++k)
            s += hf[k] * wfc[j * 128 + k];
#pragma unroll
        for (int k = 0; k < 64; ++k)
            s += hb_sh[k] * wfc[j * 128 + 64 + k];
        out[b * 12 + j] = s;
    }
}

// ---------------------------------------------------------------------------
extern "C" void kernel_launch(void* const* d_in, const int* in_sizes, int n_in,
                              void* d_out, int out_size)
{
    const int*   x      = (const int*)d_in[0];
    const float* emb    = (const float*)d_in[1];
    const float* w_ih_f = (const float*)d_in[2];
    const float* w_hh_f = (const float*)d_in[3];
    const float* b_ih_f = (const float*)d_in[4];
    const float* b_hh_f = (const float*)d_in[5];
    const float* w_ih_b = (const float*)d_in[6];
    const float* w_hh_b = (const float*)d_in[7];
    const float* b_ih_b = (const float*)d_in[8];
    const float* b_hh_b = (const float*)d_in[9];
    const float* w_fc   = (const float*)d_in[10];
    const float* b_fc   = (const float*)d_in[11];
    float* out = (float*)d_out;

    k_proj<<<(VV + 7) / 8, 256>>>(emb, w_ih_f, b_ih_f, b_hh_f);
    k_scan<<<128, 256>>>(x, w_hh_f);
    k_tail<<<BB, 256>>>(x, emb, w_ih_b, b_ih_b, b_hh_b, w_fc, b_fc, out);
}